// round 15
// baseline (speedup 1.0000x reference)
#include <cuda_runtime.h>

#define BATCHES 16
#define ELEMS_PER_BATCH (64*128*128)        // 1048576
#define VEC_PER_BATCH   (ELEMS_PER_BATCH/4) // 262144 float4/int4 per batch
#define BPB 18                              // 16*18 = 288 blocks of 512 <= 296 slots = ONE wave at 2 CTAs/SM
#define TPB 512
#define NBLOCKS (BATCHES * BPB)

__device__ double             g_sums[BATCHES][5];   // zero at launch start
__device__ unsigned long long g_cnt[BATCHES];       // zero at launch start
__device__ unsigned int       g_ticket = 0;         // reset by last block each launch

__global__ void __launch_bounds__(TPB, 2) ncc_kernel(
    const float* __restrict__ out_p,
    const float* __restrict__ ypred_p,
    const int*   __restrict__ occl_p,
    const int*   __restrict__ yccl_p,
    float*       __restrict__ res)
{
    const int b   = blockIdx.x / BPB;
    const int blk = blockIdx.x % BPB;

    const float4* I4  = (const float4*)(out_p)   + (size_t)b * VEC_PER_BATCH;
    const float4* J4  = (const float4*)(ypred_p) + (size_t)b * VEC_PER_BATCH;
    const int4*   cI4 = (const int4*)(occl_p)    + (size_t)b * VEC_PER_BATCH;
    const int4*   cJ4 = (const int4*)(yccl_p)    + (size_t)b * VEC_PER_BATCH;

    float sI = 0.f, sJ = 0.f, sI2 = 0.f, sJ2 = 0.f, sIJ = 0.f;
    int   cnt = 0;

    #define NCC_ACC(x, y, cx, cy)                                   \
    {                                                               \
        sI += (x); sJ += (y);                                       \
        sI2 = fmaf((x), (x), sI2);                                  \
        sJ2 = fmaf((y), (y), sJ2);                                  \
        sIJ = fmaf((x), (y), sIJ);                                  \
        int mI = !(((x) < 0.247f) && ((cx) > 0));                   \
        int mJ = !(((y) < 0.247f) && ((cy) > 0));                   \
        cnt += (mI & mJ);                                           \
    }
    #define NCC_ACC4(iv, jv, civ, cjv)                              \
        NCC_ACC(iv.x, jv.x, civ.x, cjv.x)                           \
        NCC_ACC(iv.y, jv.y, civ.y, cjv.y)                           \
        NCC_ACC(iv.z, jv.z, civ.z, cjv.z)                           \
        NCC_ACC(iv.w, jv.w, civ.w, cjv.w)

    const int stride = BPB * TPB;
    int i = blk * TPB + threadIdx.x;

    // Software-pipelined x4: 16 independent 16B loads in flight (MLP=16).
    // 128-reg budget from launch_bounds(512,2) holds all load data live.
    for (; i + 3 * stride < VEC_PER_BATCH; i += 4 * stride) {
        const int i1 = i + stride, i2 = i + 2 * stride, i3 = i + 3 * stride;
        float4 iv0  = __ldg(I4  + i);   float4 jv0  = __ldg(J4  + i);
        int4   civ0 = __ldg(cI4 + i);   int4   cjv0 = __ldg(cJ4 + i);
        float4 iv1  = __ldg(I4  + i1);  float4 jv1  = __ldg(J4  + i1);
        int4   civ1 = __ldg(cI4 + i1);  int4   cjv1 = __ldg(cJ4 + i1);
        float4 iv2  = __ldg(I4  + i2);  float4 jv2  = __ldg(J4  + i2);
        int4   civ2 = __ldg(cI4 + i2);  int4   cjv2 = __ldg(cJ4 + i2);
        float4 iv3  = __ldg(I4  + i3);  float4 jv3  = __ldg(J4  + i3);
        int4   civ3 = __ldg(cI4 + i3);  int4   cjv3 = __ldg(cJ4 + i3);

        NCC_ACC4(iv0, jv0, civ0, cjv0)
        NCC_ACC4(iv1, jv1, civ1, cjv1)
        NCC_ACC4(iv2, jv2, civ2, cjv2)
        NCC_ACC4(iv3, jv3, civ3, cjv3)
    }
    for (; i < VEC_PER_BATCH; i += stride) {
        float4 iv  = __ldg(I4  + i);
        float4 jv  = __ldg(J4  + i);
        int4   civ = __ldg(cI4 + i);
        int4   cjv = __ldg(cJ4 + i);
        NCC_ACC4(iv, jv, civ, cjv)
    }
    #undef NCC_ACC4
    #undef NCC_ACC

    // intra-warp reduce
    #pragma unroll
    for (int off = 16; off; off >>= 1) {
        sI  += __shfl_down_sync(0xffffffffu, sI,  off);
        sJ  += __shfl_down_sync(0xffffffffu, sJ,  off);
        sI2 += __shfl_down_sync(0xffffffffu, sI2, off);
        sJ2 += __shfl_down_sync(0xffffffffu, sJ2, off);
        sIJ += __shfl_down_sync(0xffffffffu, sIJ, off);
        cnt += __shfl_down_sync(0xffffffffu, cnt, off);
    }

    __shared__ double shS[TPB / 32][5];
    __shared__ int    shC[TPB / 32];
    __shared__ bool   s_last;
    const int lane = threadIdx.x & 31;
    const int w    = threadIdx.x >> 5;
    if (lane == 0) {
        shS[w][0] = (double)sI;  shS[w][1] = (double)sJ;
        shS[w][2] = (double)sI2; shS[w][3] = (double)sJ2;
        shS[w][4] = (double)sIJ;
        shC[w]    = cnt;
    }
    __syncthreads();

    if (w == 0) {
        double a0 = 0, a1 = 0, a2 = 0, a3 = 0, a4 = 0;
        int    c  = 0;
        if (lane < TPB / 32) {          // 16 warps per block
            a0 = shS[lane][0]; a1 = shS[lane][1]; a2 = shS[lane][2];
            a3 = shS[lane][3]; a4 = shS[lane][4]; c = shC[lane];
        }
        #pragma unroll
        for (int off = 8; off; off >>= 1) {
            a0 += __shfl_down_sync(0xffffffffu, a0, off);
            a1 += __shfl_down_sync(0xffffffffu, a1, off);
            a2 += __shfl_down_sync(0xffffffffu, a2, off);
            a3 += __shfl_down_sync(0xffffffffu, a3, off);
            a4 += __shfl_down_sync(0xffffffffu, a4, off);
            c  += __shfl_down_sync(0xffffffffu, c,  off);
        }
        if (lane == 0) {
            atomicAdd(&g_sums[b][0], a0);
            atomicAdd(&g_sums[b][1], a1);
            atomicAdd(&g_sums[b][2], a2);
            atomicAdd(&g_sums[b][3], a3);
            atomicAdd(&g_sums[b][4], a4);
            atomicAdd(&g_cnt[b], (unsigned long long)c);
            __threadfence();                              // release: publish atomics
            unsigned int t = atomicAdd(&g_ticket, 1u);
            s_last = (t == (unsigned int)(NBLOCKS - 1));
        }
    }
    __syncthreads();
    if (!s_last) return;

    // ---- last block: finalize (one warp) + reset for replay ----
    if (threadIdx.x < 32) {
        __threadfence();                                  // acquire side
        double v = 0.0;
        const int bb = threadIdx.x;
        if (bb < BATCHES) {
            volatile double* vs = &g_sums[bb][0];
            double Is = vs[0], Js = vs[1], I2 = vs[2], J2 = vs[3], IJ = vs[4];
            double cn = (double)*(volatile unsigned long long*)&g_cnt[bb];
            const double W  = (double)ELEMS_PER_BATCH;
            double uI = Is / W, uJ = Js / W;
            double cross = IJ - uJ * Is - uI * Js + uI * uJ * W;
            double Ivar  = I2 - 2.0 * uI * Is + uI * uI * W;
            double Jvar  = J2 - 2.0 * uJ * Js + uJ * uJ * W;
            double cc    = (cross * cross) / (Ivar * Jvar + 1e-5);
            v = cc * cn;

            // reset for next replay (first call starts zeroed via static init)
            vs[0] = 0.0; vs[1] = 0.0; vs[2] = 0.0; vs[3] = 0.0; vs[4] = 0.0;
            g_cnt[bb] = 0ull;
        }
        #pragma unroll
        for (int off = 16; off; off >>= 1)
            v += __shfl_down_sync(0xffffffffu, v, off);
        if (threadIdx.x == 0) {
            *res = (float)(-v / ((double)BATCHES * (double)ELEMS_PER_BATCH));
            g_ticket = 0;
        }
    }
}

extern "C" void kernel_launch(void* const* d_in, const int* in_sizes, int n_in,
                              void* d_out, int out_size) {
    const float* out_p   = (const float*)d_in[0];
    const float* ypred_p = (const float*)d_in[1];
    const int*   occl_p  = (const int*)d_in[2];
    const int*   yccl_p  = (const int*)d_in[3];

    ncc_kernel<<<NBLOCKS, TPB>>>(out_p, ypred_p, occl_p, yccl_p, (float*)d_out);
}

// round 16
// speedup vs baseline: 1.0337x; 1.0337x over previous
#include <cuda_runtime.h>

#define BATCHES 16
#define ELEMS_PER_BATCH (64*128*128)        // 1048576
#define VEC_PER_BATCH   (ELEMS_PER_BATCH/4) // 262144 float4/int4 per batch
#define BPB 37                              // 16*37 = 592 blocks = ONE wave at 4 CTAs/SM on 148 SMs
#define TPB 256
#define NBLOCKS (BATCHES * BPB)

__device__ double             g_sums[BATCHES][5];   // ΣI, ΣJ, ΣI², ΣJ², ΣIJ (zero at launch start)
__device__ unsigned long long g_cnt[BATCHES];       // count of maskI&maskJ  (zero at launch start)
__device__ unsigned int       g_ticket = 0;         // reset by last block each launch

__global__ void __launch_bounds__(TPB, 4) ncc_kernel(
    const float* __restrict__ out_p,
    const float* __restrict__ ypred_p,
    const int*   __restrict__ occl_p,
    const int*   __restrict__ yccl_p,
    float*       __restrict__ res)
{
    const int b   = blockIdx.x / BPB;
    const int blk = blockIdx.x % BPB;

    const float4* I4  = (const float4*)(out_p)   + (size_t)b * VEC_PER_BATCH;
    const float4* J4  = (const float4*)(ypred_p) + (size_t)b * VEC_PER_BATCH;
    const int4*   cI4 = (const int4*)(occl_p)    + (size_t)b * VEC_PER_BATCH;
    const int4*   cJ4 = (const int4*)(yccl_p)    + (size_t)b * VEC_PER_BATCH;

    float sI = 0.f, sJ = 0.f, sI2 = 0.f, sJ2 = 0.f, sIJ = 0.f;
    int   cnt = 0;

    #define NCC_ACC(x, y, cx, cy)                                   \
    {                                                               \
        sI += (x); sJ += (y);                                       \
        sI2 = fmaf((x), (x), sI2);                                  \
        sJ2 = fmaf((y), (y), sJ2);                                  \
        sIJ = fmaf((x), (y), sIJ);                                  \
        int mI = !(((x) < 0.247f) && ((cx) > 0));                   \
        int mJ = !(((y) < 0.247f) && ((cy) > 0));                   \
        cnt += (mI & mJ);                                           \
    }
    #define NCC_ACC4(iv, jv, civ, cjv)                              \
        NCC_ACC(iv.x, jv.x, civ.x, cjv.x)                           \
        NCC_ACC(iv.y, jv.y, civ.y, cjv.y)                           \
        NCC_ACC(iv.z, jv.z, civ.z, cjv.z)                           \
        NCC_ACC(iv.w, jv.w, civ.w, cjv.w)

    const int stride = BPB * TPB;
    int i = blk * TPB + threadIdx.x;

    // Software-pipelined x2: 8 independent 16B loads in flight (MLP=8).
    for (; i + stride < VEC_PER_BATCH; i += 2 * stride) {
        const int j = i + stride;
        float4 iv0  = __ldg(I4  + i);
        float4 jv0  = __ldg(J4  + i);
        int4   civ0 = __ldg(cI4 + i);
        int4   cjv0 = __ldg(cJ4 + i);
        float4 iv1  = __ldg(I4  + j);
        float4 jv1  = __ldg(J4  + j);
        int4   civ1 = __ldg(cI4 + j);
        int4   cjv1 = __ldg(cJ4 + j);

        NCC_ACC4(iv0, jv0, civ0, cjv0)
        NCC_ACC4(iv1, jv1, civ1, cjv1)
    }
    if (i < VEC_PER_BATCH) {
        float4 iv  = __ldg(I4  + i);
        float4 jv  = __ldg(J4  + i);
        int4   civ = __ldg(cI4 + i);
        int4   cjv = __ldg(cJ4 + i);
        NCC_ACC4(iv, jv, civ, cjv)
    }
    #undef NCC_ACC4
    #undef NCC_ACC

    // intra-warp reduce
    #pragma unroll
    for (int off = 16; off; off >>= 1) {
        sI  += __shfl_down_sync(0xffffffffu, sI,  off);
        sJ  += __shfl_down_sync(0xffffffffu, sJ,  off);
        sI2 += __shfl_down_sync(0xffffffffu, sI2, off);
        sJ2 += __shfl_down_sync(0xffffffffu, sJ2, off);
        sIJ += __shfl_down_sync(0xffffffffu, sIJ, off);
        cnt += __shfl_down_sync(0xffffffffu, cnt, off);
    }

    __shared__ double shS[TPB / 32][5];
    __shared__ int    shC[TPB / 32];
    __shared__ bool   s_last;
    const int lane = threadIdx.x & 31;
    const int w    = threadIdx.x >> 5;
    if (lane == 0) {
        shS[w][0] = (double)sI;  shS[w][1] = (double)sJ;
        shS[w][2] = (double)sI2; shS[w][3] = (double)sJ2;
        shS[w][4] = (double)sIJ;
        shC[w]    = cnt;
    }
    __syncthreads();

    if (w == 0) {
        double a0 = 0, a1 = 0, a2 = 0, a3 = 0, a4 = 0;
        int    c  = 0;
        if (lane < TPB / 32) {
            a0 = shS[lane][0]; a1 = shS[lane][1]; a2 = shS[lane][2];
            a3 = shS[lane][3]; a4 = shS[lane][4]; c = shC[lane];
        }
        #pragma unroll
        for (int off = 4; off; off >>= 1) {
            a0 += __shfl_down_sync(0xffffffffu, a0, off);
            a1 += __shfl_down_sync(0xffffffffu, a1, off);
            a2 += __shfl_down_sync(0xffffffffu, a2, off);
            a3 += __shfl_down_sync(0xffffffffu, a3, off);
            a4 += __shfl_down_sync(0xffffffffu, a4, off);
            c  += __shfl_down_sync(0xffffffffu, c,  off);
        }
        if (lane == 0) {
            atomicAdd(&g_sums[b][0], a0);
            atomicAdd(&g_sums[b][1], a1);
            atomicAdd(&g_sums[b][2], a2);
            atomicAdd(&g_sums[b][3], a3);
            atomicAdd(&g_sums[b][4], a4);
            atomicAdd(&g_cnt[b], (unsigned long long)c);
            __threadfence();                              // release: publish atomics
            unsigned int t = atomicAdd(&g_ticket, 1u);
            s_last = (t == (unsigned int)(NBLOCKS - 1));
        }
    }
    __syncthreads();
    if (!s_last) return;

    // ---- last block: finalize (one warp) ----
    if (threadIdx.x < 32) {
        __threadfence();                                  // acquire side
        double v = 0.0;
        const int bb = threadIdx.x;
        if (bb < BATCHES) {
            volatile double* vs = &g_sums[bb][0];
            double Is = vs[0], Js = vs[1], I2 = vs[2], J2 = vs[3], IJ = vs[4];
            double cn = (double)*(volatile unsigned long long*)&g_cnt[bb];
            const double W  = (double)ELEMS_PER_BATCH;
            double uI = Is / W, uJ = Js / W;
            double cross = IJ - uJ * Is - uI * Js + uI * uJ * W;
            double Ivar  = I2 - 2.0 * uI * Is + uI * uI * W;
            double Jvar  = J2 - 2.0 * uJ * Js + uJ * uJ * W;
            double cc    = (cross * cross) / (Ivar * Jvar + 1e-5);
            v = cc * cn;

            // reset for next replay (first call starts zeroed via static init)
            vs[0] = 0.0; vs[1] = 0.0; vs[2] = 0.0; vs[3] = 0.0; vs[4] = 0.0;
            g_cnt[bb] = 0ull;
        }
        #pragma unroll
        for (int off = 16; off; off >>= 1)
            v += __shfl_down_sync(0xffffffffu, v, off);
        if (threadIdx.x == 0) {
            *res = (float)(-v / ((double)BATCHES * (double)ELEMS_PER_BATCH));
            g_ticket = 0;
        }
    }
}

extern "C" void kernel_launch(void* const* d_in, const int* in_sizes, int n_in,
                              void* d_out, int out_size) {
    const float* out_p   = (const float*)d_in[0];
    const float* ypred_p = (const float*)d_in[1];
    const int*   occl_p  = (const int*)d_in[2];
    const int*   yccl_p  = (const int*)d_in[3];

    ncc_kernel<<<NBLOCKS, TPB>>>(out_p, ypred_p, occl_p, yccl_p, (float*)d_out);
}

// round 17
// speedup vs baseline: 1.0344x; 1.0007x over previous
#include <cuda_runtime.h>

#define BATCHES 16
#define ELEMS_PER_BATCH (64*128*128)        // 1048576
#define VEC_PER_BATCH   (ELEMS_PER_BATCH/4) // 262144 float4/int4 per batch
#define BPB 37                              // 16*37 = 592 blocks = ONE wave at 4 CTAs/SM on 148 SMs
#define TPB 256
#define NBLOCKS (BATCHES * BPB)

__device__ double             g_sums[BATCHES][5];   // ΣI, ΣJ, ΣI², ΣJ², ΣIJ (zero at launch start)
__device__ unsigned long long g_cnt[BATCHES];       // count of maskI&maskJ  (zero at launch start)
__device__ unsigned int       g_ticket = 0;         // reset by last block each launch

__global__ void __launch_bounds__(TPB, 4) ncc_kernel(
    const float* __restrict__ out_p,
    const float* __restrict__ ypred_p,
    const int*   __restrict__ occl_p,
    const int*   __restrict__ yccl_p,
    float*       __restrict__ res)
{
    const int b   = blockIdx.x / BPB;
    const int blk = blockIdx.x % BPB;

    const float4* I4  = (const float4*)(out_p)   + (size_t)b * VEC_PER_BATCH;
    const float4* J4  = (const float4*)(ypred_p) + (size_t)b * VEC_PER_BATCH;
    const int4*   cI4 = (const int4*)(occl_p)    + (size_t)b * VEC_PER_BATCH;
    const int4*   cJ4 = (const int4*)(yccl_p)    + (size_t)b * VEC_PER_BATCH;

    float sI = 0.f, sJ = 0.f, sI2 = 0.f, sJ2 = 0.f, sIJ = 0.f;
    int   cnt = 0;

    #define NCC_ACC(x, y, cx, cy)                                   \
    {                                                               \
        sI += (x); sJ += (y);                                       \
        sI2 = fmaf((x), (x), sI2);                                  \
        sJ2 = fmaf((y), (y), sJ2);                                  \
        sIJ = fmaf((x), (y), sIJ);                                  \
        int mI = !(((x) < 0.247f) && ((cx) > 0));                   \
        int mJ = !(((y) < 0.247f) && ((cy) > 0));                   \
        cnt += (mI & mJ);                                           \
    }
    #define NCC_ACC4(iv, jv, civ, cjv)                              \
        NCC_ACC(iv.x, jv.x, civ.x, cjv.x)                           \
        NCC_ACC(iv.y, jv.y, civ.y, cjv.y)                           \
        NCC_ACC(iv.z, jv.z, civ.z, cjv.z)                           \
        NCC_ACC(iv.w, jv.w, civ.w, cjv.w)

    const int stride = BPB * TPB;
    int i = blk * TPB + threadIdx.x;

    // Software-pipelined x2: 8 independent 16B loads in flight (MLP=8).
    for (; i + stride < VEC_PER_BATCH; i += 2 * stride) {
        const int j = i + stride;
        float4 iv0  = __ldg(I4  + i);
        float4 jv0  = __ldg(J4  + i);
        int4   civ0 = __ldg(cI4 + i);
        int4   cjv0 = __ldg(cJ4 + i);
        float4 iv1  = __ldg(I4  + j);
        float4 jv1  = __ldg(J4  + j);
        int4   civ1 = __ldg(cI4 + j);
        int4   cjv1 = __ldg(cJ4 + j);

        NCC_ACC4(iv0, jv0, civ0, cjv0)
        NCC_ACC4(iv1, jv1, civ1, cjv1)
    }
    if (i < VEC_PER_BATCH) {
        float4 iv  = __ldg(I4  + i);
        float4 jv  = __ldg(J4  + i);
        int4   civ = __ldg(cI4 + i);
        int4   cjv = __ldg(cJ4 + i);
        NCC_ACC4(iv, jv, civ, cjv)
    }
    #undef NCC_ACC4
    #undef NCC_ACC

    // intra-warp reduce
    #pragma unroll
    for (int off = 16; off; off >>= 1) {
        sI  += __shfl_down_sync(0xffffffffu, sI,  off);
        sJ  += __shfl_down_sync(0xffffffffu, sJ,  off);
        sI2 += __shfl_down_sync(0xffffffffu, sI2, off);
        sJ2 += __shfl_down_sync(0xffffffffu, sJ2, off);
        sIJ += __shfl_down_sync(0xffffffffu, sIJ, off);
        cnt += __shfl_down_sync(0xffffffffu, cnt, off);
    }

    __shared__ double shS[TPB / 32][5];
    __shared__ int    shC[TPB / 32];
    __shared__ bool   s_last;
    const int lane = threadIdx.x & 31;
    const int w    = threadIdx.x >> 5;
    if (lane == 0) {
        shS[w][0] = (double)sI;  shS[w][1] = (double)sJ;
        shS[w][2] = (double)sI2; shS[w][3] = (double)sJ2;
        shS[w][4] = (double)sIJ;
        shC[w]    = cnt;
    }
    __syncthreads();

    if (w == 0) {
        double a0 = 0, a1 = 0, a2 = 0, a3 = 0, a4 = 0;
        int    c  = 0;
        if (lane < TPB / 32) {
            a0 = shS[lane][0]; a1 = shS[lane][1]; a2 = shS[lane][2];
            a3 = shS[lane][3]; a4 = shS[lane][4]; c = shC[lane];
        }
        #pragma unroll
        for (int off = 4; off; off >>= 1) {
            a0 += __shfl_down_sync(0xffffffffu, a0, off);
            a1 += __shfl_down_sync(0xffffffffu, a1, off);
            a2 += __shfl_down_sync(0xffffffffu, a2, off);
            a3 += __shfl_down_sync(0xffffffffu, a3, off);
            a4 += __shfl_down_sync(0xffffffffu, a4, off);
            c  += __shfl_down_sync(0xffffffffu, c,  off);
        }
        if (lane == 0) {
            atomicAdd(&g_sums[b][0], a0);
            atomicAdd(&g_sums[b][1], a1);
            atomicAdd(&g_sums[b][2], a2);
            atomicAdd(&g_sums[b][3], a3);
            atomicAdd(&g_sums[b][4], a4);
            atomicAdd(&g_cnt[b], (unsigned long long)c);
            __threadfence();                              // release: publish atomics
            unsigned int t = atomicAdd(&g_ticket, 1u);
            s_last = (t == (unsigned int)(NBLOCKS - 1));
        }
    }
    __syncthreads();
    if (!s_last) return;

    // ---- last block: finalize (one warp) ----
    if (threadIdx.x < 32) {
        __threadfence();                                  // acquire side
        double v = 0.0;
        const int bb = threadIdx.x;
        if (bb < BATCHES) {
            volatile double* vs = &g_sums[bb][0];
            double Is = vs[0], Js = vs[1], I2 = vs[2], J2 = vs[3], IJ = vs[4];
            double cn = (double)*(volatile unsigned long long*)&g_cnt[bb];
            const double W  = (double)ELEMS_PER_BATCH;
            double uI = Is / W, uJ = Js / W;
            double cross = IJ - uJ * Is - uI * Js + uI * uJ * W;
            double Ivar  = I2 - 2.0 * uI * Is + uI * uI * W;
            double Jvar  = J2 - 2.0 * uJ * Js + uJ * uJ * W;
            double cc    = (cross * cross) / (Ivar * Jvar + 1e-5);
            v = cc * cn;

            // reset for next replay (first call starts zeroed via static init)
            vs[0] = 0.0; vs[1] = 0.0; vs[2] = 0.0; vs[3] = 0.0; vs[4] = 0.0;
            g_cnt[bb] = 0ull;
        }
        #pragma unroll
        for (int off = 16; off; off >>= 1)
            v += __shfl_down_sync(0xffffffffu, v, off);
        if (threadIdx.x == 0) {
            *res = (float)(-v / ((double)BATCHES * (double)ELEMS_PER_BATCH));
            g_ticket = 0;
        }
    }
}

extern "C" void kernel_launch(void* const* d_in, const int* in_sizes, int n_in,
                              void* d_out, int out_size) {
    const float* out_p   = (const float*)d_in[0];
    const float* ypred_p = (const float*)d_in[1];
    const int*   occl_p  = (const int*)d_in[2];
    const int*   yccl_p  = (const int*)d_in[3];

    ncc_kernel<<<NBLOCKS, TPB>>>(out_p, ypred_p, occl_p, yccl_p, (float*)d_out);
}